// round 13
// baseline (speedup 1.0000x reference)
#include <cuda_runtime.h>
#include <cuda.h>
#include <cuda_fp16.h>
#include <math.h>
#include <stdint.h>

#define NB 8
#define SS 2048
#define HH 1024
#define MM 1024
#define MP 1026   // padded rows per batch (zero row below m=0 and above m=1023)

#define C_H0 0.48296291314469025f
#define C_H1 0.83651630373780790f
#define C_H2 0.22414386804185735f
#define C_H3 (-0.12940952255092145f)

// GEMM tiling: CTA 128x128, BK=64, 3-stage TMA pipeline, SW128
// 8 warps (256 threads), warp tile 64x32 (2x4 warp grid), persistent CTAs,
// dynamic tile scheduler (atomic counter)
#define BK 64
#define TILEB 16384           // 128 rows x 128B per operand tile
#define STAGEB (2 * TILEB)    // A + B
#define SMEM_BYTES (3 * STAGEB + 64)

// ---------------- device scratch ----------------
__device__ __align__(16) __half g_ca[NB * MP * HH];
__device__ __align__(16) __half g_cd[NB * MP * HH];
__device__ __align__(16) __half g_pa[NB * MM * HH];
__device__ __align__(16) __half g_pd[NB * MM * HH];
__device__ __align__(16) __half g_rec[NB * SS * HH];
__device__ __align__(16) __half g_wc[2 * HH * 3072];  // [which][o][delta*1024+h]
__device__ __align__(16) __half g_wo[HH * HH];        // [o][h]
__device__ int g_ctr_conv;
__device__ int g_ctr_out;

// ---------------- helpers ----------------
__device__ __forceinline__ uint32_t smem_u32(const void* p) {
    uint32_t a;
    asm("{ .reg .u64 t; cvta.to.shared.u64 t, %1; cvt.u32.u64 %0, t; }" : "=r"(a) : "l"(p));
    return a;
}

__device__ __forceinline__ uint32_t sw128(uint32_t o) {  // SW128: bits[6:4] ^= bits[9:7]
    return o ^ ((o >> 3) & 0x70);
}

__device__ __forceinline__ void ldm_x4(uint32_t& r0, uint32_t& r1, uint32_t& r2, uint32_t& r3,
                                       uint32_t addr) {
    asm volatile("ldmatrix.sync.aligned.m8n8.x4.shared.b16 {%0,%1,%2,%3}, [%4];"
                 : "=r"(r0), "=r"(r1), "=r"(r2), "=r"(r3) : "r"(addr));
}

__device__ __forceinline__ void mma16816(float* d, const uint32_t* a, const uint32_t* b) {
    asm volatile(
        "mma.sync.aligned.m16n8k16.row.col.f32.f16.f16.f32 "
        "{%0,%1,%2,%3}, {%4,%5,%6,%7}, {%8,%9}, {%0,%1,%2,%3};"
        : "+f"(d[0]), "+f"(d[1]), "+f"(d[2]), "+f"(d[3])
        : "r"(a[0]), "r"(a[1]), "r"(a[2]), "r"(a[3]), "r"(b[0]), "r"(b[1]));
}

__device__ __forceinline__ void tma2d(uint32_t dst, const CUtensorMap* tm, int x, int y,
                                      uint32_t mb) {
    asm volatile(
        "cp.async.bulk.tensor.2d.shared::cta.global.tile.mbarrier::complete_tx::bytes "
        "[%0], [%1, {%2, %3}], [%4];"
        :: "r"(dst), "l"(tm), "r"(x), "r"(y), "r"(mb) : "memory");
}

__device__ __forceinline__ void mbar_init(uint32_t mb, uint32_t cnt) {
    asm volatile("mbarrier.init.shared.b64 [%0], %1;" :: "r"(mb), "r"(cnt) : "memory");
}

__device__ __forceinline__ void mbar_expect(uint32_t mb, uint32_t bytes) {
    asm volatile("mbarrier.arrive.expect_tx.shared.b64 _, [%0], %1;"
                 :: "r"(mb), "r"(bytes) : "memory");
}

__device__ __forceinline__ void mbar_wait(uint32_t mb, uint32_t parity) {
    asm volatile(
        "{\n\t.reg .pred P;\n\t"
        "LAB_%=:\n\t"
        "mbarrier.try_wait.parity.acquire.cta.shared::cta.b64 P, [%0], %1, 0x989680;\n\t"
        "@!P bra LAB_%=;\n\t"
        "}" :: "r"(mb), "r"(parity) : "memory");
}

__device__ __forceinline__ float gelu_exact(float v) {
    return 0.5f * v * (1.0f + erff(v * 0.70710678118654752f));
}

// ---------------- weight prep (fused: conv + out weights + scheduler reset) ---
__global__ void prep_weights(const float* __restrict__ wA, const float* __restrict__ wD,
                             const float* __restrict__ wO, int nPersist) {
    int idx = blockIdx.x * 256 + threadIdx.x;
    if (idx == 0) {
        g_ctr_conv = nPersist;
        g_ctr_out = nPersist;
    }
    if (idx < (2 << 20)) {                   // conv weights: 2 * 1M entries (o,h)
        int which = idx >> 20;
        int oh = idx & ((1 << 20) - 1);
        int o = oh >> 10, h = oh & 1023;
        const float* w = which ? wD : wA;
        __half* W = g_wc + (size_t)which * HH * 3072;
        const float* p = w + ((size_t)o * HH + h) * 3;
#pragma unroll
        for (int d = 0; d < 3; d++)
            W[(size_t)o * 3072 + d * 1024 + h] = __float2half_rn(p[d]);
    } else {                                 // out weights: 1M entries
        int j = idx - (2 << 20);
        g_wo[j] = __float2half_rn(wO[j]);
    }
}

// ---------------- DWT -> fp16 (padded rows) + boundary zero rows ----------------
__global__ void dwt_kernel(const float* __restrict__ x) {
    int bm = blockIdx.x;
    if (bm >= NB * MM) {                     // 16 extra blocks: zero pad rows
        int j = bm - NB * MM;
        int b = j >> 1;
        int top = j & 1;
        size_t off = ((size_t)b * MP + (top ? 1025 : 0)) * HH + threadIdx.x * 4;
        uint2 z = make_uint2(0u, 0u);
        *(uint2*)(g_ca + off) = z;
        *(uint2*)(g_cd + off) = z;
        return;
    }
    int b = bm >> 10, m = bm & 1023;
    int h = threadIdx.x << 2;
    int s0 = 2 * m - 2, s1 = 2 * m - 1;
    if (s0 < 0) s0 = -s0 - 1;
    if (s1 < 0) s1 = -s1 - 1;
    const float* xb = x + (size_t)b * SS * HH + h;
    float4 v0 = *(const float4*)(xb + (size_t)s0 * HH);
    float4 v1 = *(const float4*)(xb + (size_t)s1 * HH);
    float4 v2 = *(const float4*)(xb + (size_t)(2 * m) * HH);
    float4 v3 = *(const float4*)(xb + (size_t)(2 * m + 1) * HH);
    __half ca[4], cd[4];
    ca[0] = __float2half_rn(C_H0 * v0.x + C_H1 * v1.x + C_H2 * v2.x + C_H3 * v3.x);
    ca[1] = __float2half_rn(C_H0 * v0.y + C_H1 * v1.y + C_H2 * v2.y + C_H3 * v3.y);
    ca[2] = __float2half_rn(C_H0 * v0.z + C_H1 * v1.z + C_H2 * v2.z + C_H3 * v3.z);
    ca[3] = __float2half_rn(C_H0 * v0.w + C_H1 * v1.w + C_H2 * v2.w + C_H3 * v3.w);
    cd[0] = __float2half_rn(C_H3 * v0.x - C_H2 * v1.x + C_H1 * v2.x - C_H0 * v3.x);
    cd[1] = __float2half_rn(C_H3 * v0.y - C_H2 * v1.y + C_H1 * v2.y - C_H0 * v3.y);
    cd[2] = __float2half_rn(C_H3 * v0.z - C_H2 * v1.z + C_H1 * v2.z - C_H0 * v3.z);
    cd[3] = __float2half_rn(C_H3 * v0.w - C_H2 * v1.w + C_H1 * v2.w - C_H0 * v3.w);
    size_t off = ((size_t)b * MP + m + 1) * HH + h;
    *(uint2*)(g_ca + off) = *(const uint2*)ca;
    *(uint2*)(g_cd + off) = *(const uint2*)cd;
}

// ---------------- paired iDWT: rows 2t and 2t+1 share the same 4 source rows ----
__global__ void idwt_kernel() {
    int bt = blockIdx.x;
    int b = bt >> 10, t = bt & 1023;
    int h = threadIdx.x << 2;
    size_t outoff = ((size_t)b * SS + 2 * t) * HH + h;
    if (t == 1023) {   // rows 2046, 2047 are zero
        uint2 z = make_uint2(0u, 0u);
        *(uint2*)(g_rec + outoff) = z;
        *(uint2*)(g_rec + outoff + HH) = z;
        return;
    }
    size_t base = (size_t)b * MM * HH + h + (size_t)t * HH;
    uint2 ua0 = *(const uint2*)(g_pa + base);
    uint2 ua1 = *(const uint2*)(g_pa + base + HH);
    uint2 ud0 = *(const uint2*)(g_pd + base);
    uint2 ud1 = *(const uint2*)(g_pd + base + HH);
    const __half2* a0 = (const __half2*)&ua0;
    const __half2* a1 = (const __half2*)&ua1;
    const __half2* d0 = (const __half2*)&ud0;
    const __half2* d1 = (const __half2*)&ud1;
    __half ev[4], od[4];
#pragma unroll
    for (int q = 0; q < 2; q++) {
        float2 fa0 = __half22float2(a0[q]);
        float2 fa1 = __half22float2(a1[q]);
        float2 fd0 = __half22float2(d0[q]);
        float2 fd1 = __half22float2(d1[q]);
        ev[2 * q + 0] = __float2half_rn(C_H2 * fa0.x + C_H0 * fa1.x + C_H1 * fd0.x + C_H3 * fd1.x);
        ev[2 * q + 1] = __float2half_rn(C_H2 * fa0.y + C_H0 * fa1.y + C_H1 * fd0.y + C_H3 * fd1.y);
        od[2 * q + 0] = __float2half_rn(C_H3 * fa0.x + C_H1 * fa1.x - C_H0 * fd0.x - C_H2 * fd1.x);
        od[2 * q + 1] = __float2half_rn(C_H3 * fa0.y + C_H1 * fa1.y - C_H0 * fd0.y - C_H2 * fd1.y);
    }
    *(uint2*)(g_rec + outoff) = *(const uint2*)ev;
    *(uint2*)(g_rec + outoff + HH) = *(const uint2*)od;
}

// ---------------------------------------------------------------------------
// Persistent fp16 GEMM, TMA-fed, continuous 3-stage pipeline, DYNAMIC tile
// scheduler: producer claims the next tile (atomicAdd) exactly when the
// 2-chunk lookahead crosses the tile boundary (c == kChunks-2), so the next
// tile's first chunks stream in during this tile's tail + epilogue.
// Tile decode: which = tile>>9 (CONV), row0 = ((tile>>3)&63)<<7 (CONV) or
// (tile>>3)<<7, col0 = (tile&7)<<7.
// ---------------------------------------------------------------------------
template <bool CONV, bool GELU, typename OT>
__device__ __forceinline__ void persistent_gemm(
    const CUtensorMap* tmA0, const CUtensorMap* tmA1,
    const CUtensorMap* tmB0, const CUtensorMap* tmB1,
    const float* __restrict__ bias0, const float* __restrict__ bias1,
    OT* __restrict__ C0, OT* __restrict__ C1,
    int nTiles, int kChunks, int* ctr, char* smem) {

    const uint32_t sbase = smem_u32(smem);
    const uint32_t mbars = sbase + 3 * STAGEB;
    __shared__ int s_next;

    const int tid = threadIdx.x;
    const int lane = tid & 31;
    const int wid = tid >> 5;

    int curTile = blockIdx.x;
    if (curTile >= nTiles) return;

    if (tid == 0) {
        mbar_init(mbars + 0, 1);
        mbar_init(mbars + 8, 1);
        mbar_init(mbars + 16, 1);
    }
    __syncthreads();

    auto issueT = [&](int tile2, int c2, int s2) {
        const int which2 = CONV ? (tile2 >> 9) : 0;
        const int row02 = CONV ? (((tile2 >> 3) & 63) << 7) : ((tile2 >> 3) << 7);
        const int col02 = (tile2 & 7) << 7;
        const int k0 = c2 * BK;
        int ax, ay;
        if (CONV) {
            ax = k0 & 1023;
            ay = (row02 >> 10) * MP + (row02 & 1023) + (k0 >> 10);
        } else {
            ax = k0;
            ay = row02;
        }
        const uint32_t mb = mbars + s2 * 8;
        mbar_expect(mb, 2 * TILEB);
        tma2d(sbase + s2 * STAGEB, which2 ? tmA1 : tmA0, ax, ay, mb);
        tma2d(sbase + s2 * STAGEB + TILEB, which2 ? tmB1 : tmB0, k0, col02, mb);
    };

    if (tid == 0) {
        issueT(curTile, 0, 0);
        issueT(curTile, 1, 1);
    }

    // warp grid 2x4, warp tile 64x32
    const int wm = (wid >> 2) * 64;
    const int wn = (wid & 3) * 32;
    const uint32_t aBase = (uint32_t)((wm + (lane & 15)) * 128 + ((lane >> 4) << 4));
    const uint32_t bBase = (uint32_t)((wn + (lane & 7) + ((lane >> 4) << 3)) * 128 +
                                      (((lane >> 3) & 1) << 4));
    const int g8 = lane >> 2, t4 = lane & 3;

    int g = 0;        // continuous chunk counter (stage/parity)
    int ntReg = 0;    // producer-thread copy of next tile
    while (true) {
        const int which = CONV ? (curTile >> 9) : 0;
        const int row0 = CONV ? (((curTile >> 3) & 63) << 7) : ((curTile >> 3) << 7);
        const int col0 = (curTile & 7) << 7;
        const float* bias = which ? bias1 : bias0;
        OT* C = which ? C1 : C0;

        float acc[4][4][4];
#pragma unroll
        for (int i = 0; i < 4; i++)
#pragma unroll
            for (int j = 0; j < 4; j++)
#pragma unroll
                for (int e = 0; e < 4; e++) acc[i][j][e] = 0.0f;

        for (int c = 0; c < kChunks; c++, g++) {
            __syncthreads();   // everyone done with stage (g+2)%3's previous use

            if (tid == 0) {
                const int cc = c + 2;
                const int s2 = (g + 2) % 3;
                if (cc < kChunks) {
                    issueT(curTile, cc, s2);
                } else {
                    if (cc == kChunks) {          // first boundary crossing: claim next tile
                        ntReg = atomicAdd(ctr, 1);
                        s_next = ntReg;
                    }
                    if (ntReg < nTiles) issueT(ntReg, cc - kChunks, s2);
                }
            }

            const int s = g % 3;
            mbar_wait(mbars + s * 8, (uint32_t)((g / 3) & 1));

            const uint32_t stA = sbase + s * STAGEB;
            const uint32_t stB = stA + TILEB;
#pragma unroll
            for (int kk = 0; kk < 4; kk++) {
                uint32_t af[4][4];
#pragma unroll
                for (int mt = 0; mt < 4; mt++) {
                    const uint32_t lo = aBase + mt * (16 * 128) + kk * 32;
                    ldm_x4(af[mt][0], af[mt][1], af[mt][2], af[mt][3], stA + sw128(lo));
                }
                uint32_t bf[4][2];
#pragma unroll
                for (int nt2 = 0; nt2 < 2; nt2++) {
                    const uint32_t lo = bBase + nt2 * (16 * 128) + kk * 32;
                    ldm_x4(bf[2 * nt2][0], bf[2 * nt2][1], bf[2 * nt2 + 1][0],
                           bf[2 * nt2 + 1][1], stB + sw128(lo));
                }
#pragma unroll
                for (int mt = 0; mt < 4; mt++)
#pragma unroll
                    for (int nt = 0; nt < 4; nt++)
                        mma16816(acc[mt][nt], af[mt], bf[nt]);
            }
        }

        // ---- epilogue (overlaps with TMA of next tile's first chunks)
#pragma unroll
        for (int mt = 0; mt < 4; mt++) {
            const int m = row0 + wm + mt * 16 + g8;
            OT* crow0 = C + (size_t)m * HH;
            OT* crow1 = crow0 + 8 * HH;
#pragma unroll
            for (int nt = 0; nt < 4; nt++) {
                const int n = col0 + wn + nt * 8 + 2 * t4;
                const float b0 = bias[n], b1 = bias[n + 1];
                float v0 = acc[mt][nt][0] + b0;
                float v1 = acc[mt][nt][1] + b1;
                float v2 = acc[mt][nt][2] + b0;
                float v3 = acc[mt][nt][3] + b1;
                if (GELU) {
                    v0 = gelu_exact(v0); v1 = gelu_exact(v1);
                    v2 = gelu_exact(v2); v3 = gelu_exact(v3);
                }
                if (sizeof(OT) == 2) {
                    *(__half2*)(crow0 + n) = __floats2half2_rn(v0, v1);
                    *(__half2*)(crow1 + n) = __floats2half2_rn(v2, v3);
                } else {
                    *(float2*)((float*)crow0 + n) = make_float2(v0, v1);
                    *(float2*)((float*)crow1 + n) = make_float2(v2, v3);
                }
            }
        }

        // s_next was written at c==kChunks-2 and published by the c==kChunks-1
        // __syncthreads, so it is safe to read here.
        curTile = s_next;
        if (curTile >= nTiles) break;
    }
}

// conv GEMMs: tiles 0..511 = approx, 512..1023 = detail
__global__ __launch_bounds__(256, 2)
void conv_gemm(const __grid_constant__ CUtensorMap tmAca,
               const __grid_constant__ CUtensorMap tmAcd,
               const __grid_constant__ CUtensorMap tmBa,
               const __grid_constant__ CUtensorMap tmBd,
               const float* __restrict__ bias_a, const float* __restrict__ bias_d) {
    extern __shared__ __align__(1024) char smem[];
    persistent_gemm<true, true, __half>(&tmAca, &tmAcd, &tmBa, &tmBd,
                                        bias_a, bias_d, g_pa, g_pd, 1024, 48,
                                        &g_ctr_conv, smem);
}

__global__ __launch_bounds__(256, 2)
void out_gemm(const __grid_constant__ CUtensorMap tmA,
              const __grid_constant__ CUtensorMap tmB,
              const float* __restrict__ b_out, float* __restrict__ out) {
    extern __shared__ __align__(1024) char smem[];
    persistent_gemm<false, false, float>(&tmA, &tmA, &tmB, &tmB,
                                         b_out, b_out, out, out, 1024, 16,
                                         &g_ctr_out, smem);
}

// ---------------------------------------------------------------------------
typedef CUresult (*PFN_encode)(
    CUtensorMap*, CUtensorMapDataType, cuuint32_t, void*,
    const cuuint64_t*, const cuuint64_t*, const cuuint32_t*, const cuuint32_t*,
    CUtensorMapInterleave, CUtensorMapSwizzle, CUtensorMapL2promotion,
    CUtensorMapFloatOOBfill);

static void enc2d(PFN_encode enc, CUtensorMap* tm, void* base,
                  unsigned long long inner, unsigned long long rows) {
    cuuint64_t dims[2] = {inner, rows};
    cuuint64_t strides[1] = {inner * 2};
    cuuint32_t box[2] = {64, 128};
    cuuint32_t es[2] = {1, 1};
    enc(tm, CU_TENSOR_MAP_DATA_TYPE_UINT16, 2, base, dims, strides, box, es,
        CU_TENSOR_MAP_INTERLEAVE_NONE, CU_TENSOR_MAP_SWIZZLE_128B,
        CU_TENSOR_MAP_L2_PROMOTION_L2_128B, CU_TENSOR_MAP_FLOAT_OOB_FILL_NONE);
}

extern "C" void kernel_launch(void* const* d_in, const int* in_sizes, int n_in,
                              void* d_out, int out_size) {
    const float* x        = (const float*)d_in[0];
    const float* w_approx = (const float*)d_in[1];
    const float* b_approx = (const float*)d_in[2];
    const float* w_detail = (const float*)d_in[3];
    const float* b_detail = (const float*)d_in[4];
    const float* w_out    = (const float*)d_in[5];
    const float* b_out    = (const float*)d_in[6];
    float* out = (float*)d_out;

    cudaFuncSetAttribute(conv_gemm, cudaFuncAttributeMaxDynamicSharedMemorySize, SMEM_BYTES);
    cudaFuncSetAttribute(out_gemm, cudaFuncAttributeMaxDynamicSharedMemorySize, SMEM_BYTES);

    int smCount = 148;
    cudaDeviceGetAttribute(&smCount, cudaDevAttrMultiProcessorCount, 0);
    const int nPersist = smCount * 2;

    void *p_ca, *p_cd, *p_rec, *p_wc, *p_wo;
    cudaGetSymbolAddress(&p_ca, g_ca);
    cudaGetSymbolAddress(&p_cd, g_cd);
    cudaGetSymbolAddress(&p_rec, g_rec);
    cudaGetSymbolAddress(&p_wc, g_wc);
    cudaGetSymbolAddress(&p_wo, g_wo);

    void* fn = nullptr;
    cudaDriverEntryPointQueryResult qr;
    cudaGetDriverEntryPoint("cuTensorMapEncodeTiled", &fn, cudaEnableDefault, &qr);
    PFN_encode enc = (PFN_encode)fn;

    CUtensorMap tmAca, tmAcd, tmBa, tmBd, tmArec, tmBo;
    enc2d(enc, &tmAca, p_ca, 1024, (unsigned long long)NB * MP);
    enc2d(enc, &tmAcd, p_cd, 1024, (unsigned long long)NB * MP);
    enc2d(enc, &tmBa, p_wc, 3072, 1024);
    enc2d(enc, &tmBd, (char*)p_wc + (size_t)HH * 3072 * 2, 3072, 1024);
    enc2d(enc, &tmArec, p_rec, 1024, (unsigned long long)NB * SS);
    enc2d(enc, &tmBo, p_wo, 1024, 1024);

    // fused weight prep + scheduler counter reset
    prep_weights<<<12288, 256>>>(w_approx, w_detail, w_out, nPersist);
    // fused DWT + zero-pad
    dwt_kernel<<<NB * MM + 16, 256>>>(x);

    // conv GEMMs: persistent + dynamic scheduler, 1024 tiles, K=3072
    conv_gemm<<<nPersist, 256, SMEM_BYTES>>>(tmAca, tmAcd, tmBa, tmBd,
                                             b_approx, b_detail);

    // paired iDWT: one block per (b, t) writes rows 2t, 2t+1
    idwt_kernel<<<NB * MM, 256>>>();

    // out GEMM: persistent + dynamic scheduler, 1024 tiles, K=1024
    out_gemm<<<nPersist, 256, SMEM_BYTES>>>(tmArec, tmBo, b_out, out);
}

// round 14
// speedup vs baseline: 1.1112x; 1.1112x over previous
#include <cuda_runtime.h>
#include <cuda.h>
#include <cuda_fp16.h>
#include <math.h>
#include <stdint.h>

#define NB 8
#define SS 2048
#define HH 1024
#define MM 1024
#define MP 1026   // padded rows per batch (zero row below m=0 and above m=1023)

#define C_H0 0.48296291314469025f
#define C_H1 0.83651630373780790f
#define C_H2 0.22414386804185735f
#define C_H3 (-0.12940952255092145f)

// GEMM tiling: CTA 128x128, BK=64, 3-stage TMA pipeline, SW128
// 8 warps (256 threads), warp tile 64x32 (2x4 warp grid), persistent CTAs
#define BK 64
#define TILEB 16384           // 128 rows x 128B per operand tile
#define STAGEB (2 * TILEB)    // A + B
#define SMEM_BYTES (3 * STAGEB + 64)

// ---------------- device scratch ----------------
__device__ __align__(16) __half g_ca[NB * MP * HH];
__device__ __align__(16) __half g_cd[NB * MP * HH];
__device__ __align__(16) __half g_pa[NB * MM * HH];
__device__ __align__(16) __half g_pd[NB * MM * HH];
__device__ __align__(16) __half g_rec[NB * SS * HH];
__device__ __align__(16) __half g_wc[2 * HH * 3072];  // [which][o][delta*1024+h]
__device__ __align__(16) __half g_wo[HH * HH];        // [o][h]

// ---------------- helpers ----------------
__device__ __forceinline__ uint32_t smem_u32(const void* p) {
    uint32_t a;
    asm("{ .reg .u64 t; cvta.to.shared.u64 t, %1; cvt.u32.u64 %0, t; }" : "=r"(a) : "l"(p));
    return a;
}

__device__ __forceinline__ uint32_t sw128(uint32_t o) {  // SW128: bits[6:4] ^= bits[9:7]
    return o ^ ((o >> 3) & 0x70);
}

__device__ __forceinline__ void ldm_x4(uint32_t& r0, uint32_t& r1, uint32_t& r2, uint32_t& r3,
                                       uint32_t addr) {
    asm volatile("ldmatrix.sync.aligned.m8n8.x4.shared.b16 {%0,%1,%2,%3}, [%4];"
                 : "=r"(r0), "=r"(r1), "=r"(r2), "=r"(r3) : "r"(addr));
}

__device__ __forceinline__ void mma16816(float* d, const uint32_t* a, const uint32_t* b) {
    asm volatile(
        "mma.sync.aligned.m16n8k16.row.col.f32.f16.f16.f32 "
        "{%0,%1,%2,%3}, {%4,%5,%6,%7}, {%8,%9}, {%0,%1,%2,%3};"
        : "+f"(d[0]), "+f"(d[1]), "+f"(d[2]), "+f"(d[3])
        : "r"(a[0]), "r"(a[1]), "r"(a[2]), "r"(a[3]), "r"(b[0]), "r"(b[1]));
}

__device__ __forceinline__ void tma2d(uint32_t dst, const CUtensorMap* tm, int x, int y,
                                      uint32_t mb) {
    asm volatile(
        "cp.async.bulk.tensor.2d.shared::cta.global.tile.mbarrier::complete_tx::bytes "
        "[%0], [%1, {%2, %3}], [%4];"
        :: "r"(dst), "l"(tm), "r"(x), "r"(y), "r"(mb) : "memory");
}

__device__ __forceinline__ void mbar_init(uint32_t mb, uint32_t cnt) {
    asm volatile("mbarrier.init.shared.b64 [%0], %1;" :: "r"(mb), "r"(cnt) : "memory");
}

__device__ __forceinline__ void mbar_expect(uint32_t mb, uint32_t bytes) {
    asm volatile("mbarrier.arrive.expect_tx.shared.b64 _, [%0], %1;"
                 :: "r"(mb), "r"(bytes) : "memory");
}

__device__ __forceinline__ void mbar_wait(uint32_t mb, uint32_t parity) {
    asm volatile(
        "{\n\t.reg .pred P;\n\t"
        "LAB_%=:\n\t"
        "mbarrier.try_wait.parity.acquire.cta.shared::cta.b64 P, [%0], %1, 0x989680;\n\t"
        "@!P bra LAB_%=;\n\t"
        "}" :: "r"(mb), "r"(parity) : "memory");
}

__device__ __forceinline__ float gelu_exact(float v) {
    return 0.5f * v * (1.0f + erff(v * 0.70710678118654752f));
}

// ---------------- weight prep (fused: conv + out weights) ----------------
__global__ void prep_weights(const float* __restrict__ wA, const float* __restrict__ wD,
                             const float* __restrict__ wO) {
    int idx = blockIdx.x * 256 + threadIdx.x;
    if (idx < (2 << 20)) {                   // conv weights: 2 * 1M entries (o,h)
        int which = idx >> 20;
        int oh = idx & ((1 << 20) - 1);
        int o = oh >> 10, h = oh & 1023;
        const float* w = which ? wD : wA;
        __half* W = g_wc + (size_t)which * HH * 3072;
        const float* p = w + ((size_t)o * HH + h) * 3;
#pragma unroll
        for (int d = 0; d < 3; d++)
            W[(size_t)o * 3072 + d * 1024 + h] = __float2half_rn(p[d]);
    } else {                                 // out weights: 1M entries
        int j = idx - (2 << 20);
        g_wo[j] = __float2half_rn(wO[j]);
    }
}

// ---------------- DWT -> fp16 (padded rows) + boundary zero rows ----------------
__global__ void dwt_kernel(const float* __restrict__ x) {
    int bm = blockIdx.x;
    if (bm >= NB * MM) {                     // 16 extra blocks: zero pad rows
        int j = bm - NB * MM;
        int b = j >> 1;
        int top = j & 1;
        size_t off = ((size_t)b * MP + (top ? 1025 : 0)) * HH + threadIdx.x * 4;
        uint2 z = make_uint2(0u, 0u);
        *(uint2*)(g_ca + off) = z;
        *(uint2*)(g_cd + off) = z;
        return;
    }
    int b = bm >> 10, m = bm & 1023;
    int h = threadIdx.x << 2;
    int s0 = 2 * m - 2, s1 = 2 * m - 1;
    if (s0 < 0) s0 = -s0 - 1;
    if (s1 < 0) s1 = -s1 - 1;
    const float* xb = x + (size_t)b * SS * HH + h;
    float4 v0 = *(const float4*)(xb + (size_t)s0 * HH);
    float4 v1 = *(const float4*)(xb + (size_t)s1 * HH);
    float4 v2 = *(const float4*)(xb + (size_t)(2 * m) * HH);
    float4 v3 = *(const float4*)(xb + (size_t)(2 * m + 1) * HH);
    __half ca[4], cd[4];
    ca[0] = __float2half_rn(C_H0 * v0.x + C_H1 * v1.x + C_H2 * v2.x + C_H3 * v3.x);
    ca[1] = __float2half_rn(C_H0 * v0.y + C_H1 * v1.y + C_H2 * v2.y + C_H3 * v3.y);
    ca[2] = __float2half_rn(C_H0 * v0.z + C_H1 * v1.z + C_H2 * v2.z + C_H3 * v3.z);
    ca[3] = __float2half_rn(C_H0 * v0.w + C_H1 * v1.w + C_H2 * v2.w + C_H3 * v3.w);
    cd[0] = __float2half_rn(C_H3 * v0.x - C_H2 * v1.x + C_H1 * v2.x - C_H0 * v3.x);
    cd[1] = __float2half_rn(C_H3 * v0.y - C_H2 * v1.y + C_H1 * v2.y - C_H0 * v3.y);
    cd[2] = __float2half_rn(C_H3 * v0.z - C_H2 * v1.z + C_H1 * v2.z - C_H0 * v3.z);
    cd[3] = __float2half_rn(C_H3 * v0.w - C_H2 * v1.w + C_H1 * v2.w - C_H0 * v3.w);
    size_t off = ((size_t)b * MP + m + 1) * HH + h;
    *(uint2*)(g_ca + off) = *(const uint2*)ca;
    *(uint2*)(g_cd + off) = *(const uint2*)cd;
}

// ---------------- paired iDWT, wide: 128 threads x 8 halves (uint4) ----------
// even (n=2t):   H2*pa[t] + H0*pa[t+1] + H1*pd[t] + H3*pd[t+1]
// odd  (n=2t+1): H3*pa[t] + H1*pa[t+1] - H0*pd[t] - H2*pd[t+1]
__global__ void idwt_kernel() {
    int bt = blockIdx.x;
    int b = bt >> 10, t = bt & 1023;
    int h = threadIdx.x << 3;
    size_t outoff = ((size_t)b * SS + 2 * t) * HH + h;
    if (t == 1023) {   // rows 2046, 2047 are zero
        uint4 z = make_uint4(0u, 0u, 0u, 0u);
        *(uint4*)(g_rec + outoff) = z;
        *(uint4*)(g_rec + outoff + HH) = z;
        return;
    }
    size_t base = (size_t)b * MM * HH + h + (size_t)t * HH;
    uint4 ua0 = *(const uint4*)(g_pa + base);
    uint4 ua1 = *(const uint4*)(g_pa + base + HH);
    uint4 ud0 = *(const uint4*)(g_pd + base);
    uint4 ud1 = *(const uint4*)(g_pd + base + HH);
    const __half2* a0 = (const __half2*)&ua0;
    const __half2* a1 = (const __half2*)&ua1;
    const __half2* d0 = (const __half2*)&ud0;
    const __half2* d1 = (const __half2*)&ud1;
    uint4 evo, odo;
    __half2* ev = (__half2*)&evo;
    __half2* od = (__half2*)&odo;
#pragma unroll
    for (int q = 0; q < 4; q++) {
        float2 fa0 = __half22float2(a0[q]);
        float2 fa1 = __half22float2(a1[q]);
        float2 fd0 = __half22float2(d0[q]);
        float2 fd1 = __half22float2(d1[q]);
        ev[q] = __floats2half2_rn(
            C_H2 * fa0.x + C_H0 * fa1.x + C_H1 * fd0.x + C_H3 * fd1.x,
            C_H2 * fa0.y + C_H0 * fa1.y + C_H1 * fd0.y + C_H3 * fd1.y);
        od[q] = __floats2half2_rn(
            C_H3 * fa0.x + C_H1 * fa1.x - C_H0 * fd0.x - C_H2 * fd1.x,
            C_H3 * fa0.y + C_H1 * fa1.y - C_H0 * fd0.y - C_H2 * fd1.y);
    }
    *(uint4*)(g_rec + outoff) = evo;
    *(uint4*)(g_rec + outoff + HH) = odo;
}

// ---------------------------------------------------------------------------
// Persistent fp16 GEMM, TMA-fed, R10 chunk loop, cross-tile pipelined (R12):
// a CTA processes tiles blockIdx.x, +gridDim.x, ... with a CONTINUOUS global
// chunk counter g (stage=g%3, parity=(g/3)&1). Producer issues chunk g+2,
// which near tile boundaries belongs to the NEXT tile, so its loads overlap
// this tile's epilogue.
// ---------------------------------------------------------------------------
template <bool CONV, bool GELU, typename OT>
__device__ __forceinline__ void persistent_gemm(
    const CUtensorMap* tmA0, const CUtensorMap* tmA1,
    const CUtensorMap* tmB0, const CUtensorMap* tmB1,
    const float* __restrict__ bias0, const float* __restrict__ bias1,
    OT* __restrict__ C0, OT* __restrict__ C1,
    int nTiles, int kChunks, char* smem) {

    const uint32_t sbase = smem_u32(smem);
    const uint32_t mbars = sbase + 3 * STAGEB;

    const int tid = threadIdx.x;
    const int lane = tid & 31;
    const int wid = tid >> 5;

    const int nMine = (nTiles - (int)blockIdx.x + (int)gridDim.x - 1) / (int)gridDim.x;
    if (nMine <= 0) return;
    const int totalC = nMine * kChunks;

    if (tid == 0) {
        mbar_init(mbars + 0, 1);
        mbar_init(mbars + 8, 1);
        mbar_init(mbars + 16, 1);
    }
    __syncthreads();

    // issue chunk with global (per-CTA) index gg
    auto issue = [&](int gg) {
        const int tL = gg / kChunks;
        const int c2 = gg - tL * kChunks;
        const int tile2 = (int)blockIdx.x + tL * (int)gridDim.x;
        const int which2 = CONV ? (tile2 >> 9) : 0;
        const int row02 = CONV ? (((tile2 >> 3) & 63) << 7) : ((tile2 >> 3) << 7);
        const int col02 = (tile2 & 7) << 7;
        const int k0 = c2 * BK;
        int ax, ay;
        if (CONV) {
            ax = k0 & 1023;
            ay = (row02 >> 10) * MP + (row02 & 1023) + (k0 >> 10);
        } else {
            ax = k0;
            ay = row02;
        }
        const int s2 = gg % 3;
        const uint32_t mb = mbars + s2 * 8;
        mbar_expect(mb, 2 * TILEB);
        tma2d(sbase + s2 * STAGEB, which2 ? tmA1 : tmA0, ax, ay, mb);
        tma2d(sbase + s2 * STAGEB + TILEB, which2 ? tmB1 : tmB0, k0, col02, mb);
    };

    if (tid == 0) {
        issue(0);
        if (totalC > 1) issue(1);
    }

    // warp grid 2x4, warp tile 64x32
    const int wm = (wid >> 2) * 64;
    const int wn = (wid & 3) * 32;
    const uint32_t aBase = (uint32_t)((wm + (lane & 15)) * 128 + ((lane >> 4) << 4));
    const uint32_t bBase = (uint32_t)((wn + (lane & 7) + ((lane >> 4) << 3)) * 128 +
                                      (((lane >> 3) & 1) << 4));
    const int g8 = lane >> 2, t4 = lane & 3;

    int g = 0;
    for (int myT = 0; myT < nMine; myT++) {
        const int tile = (int)blockIdx.x + myT * (int)gridDim.x;
        const int which = CONV ? (tile >> 9) : 0;
        const int row0 = CONV ? (((tile >> 3) & 63) << 7) : ((tile >> 3) << 7);
        const int col0 = (tile & 7) << 7;
        const float* bias = which ? bias1 : bias0;
        OT* C = which ? C1 : C0;

        float acc[4][4][4];
#pragma unroll
        for (int i = 0; i < 4; i++)
#pragma unroll
            for (int j = 0; j < 4; j++)
#pragma unroll
                for (int e = 0; e < 4; e++) acc[i][j][e] = 0.0f;

        for (int c = 0; c < kChunks; c++, g++) {
            __syncthreads();   // everyone done with stage (g+2)%3's previous use
            if (tid == 0 && g + 2 < totalC) issue(g + 2);

            const int s = g % 3;
            mbar_wait(mbars + s * 8, (uint32_t)((g / 3) & 1));

            const uint32_t stA = sbase + s * STAGEB;
            const uint32_t stB = stA + TILEB;
#pragma unroll
            for (int kk = 0; kk < 4; kk++) {
                uint32_t af[4][4];
#pragma unroll
                for (int mt = 0; mt < 4; mt++) {
                    const uint32_t lo = aBase + mt * (16 * 128) + kk * 32;
                    ldm_x4(af[mt][0], af[mt][1], af[mt][2], af[mt][3], stA + sw128(lo));
                }
                uint32_t bf[4][2];
#pragma unroll
                for (int nt2 = 0; nt2 < 2; nt2++) {
                    const uint32_t lo = bBase + nt2 * (16 * 128) + kk * 32;
                    ldm_x4(bf[2 * nt2][0], bf[2 * nt2][1], bf[2 * nt2 + 1][0],
                           bf[2 * nt2 + 1][1], stB + sw128(lo));
                }
#pragma unroll
                for (int mt = 0; mt < 4; mt++)
#pragma unroll
                    for (int nt = 0; nt < 4; nt++)
                        mma16816(acc[mt][nt], af[mt], bf[nt]);
            }
        }

        // ---- epilogue (overlaps with TMA of next tile's first chunks)
#pragma unroll
        for (int mt = 0; mt < 4; mt++) {
            const int m = row0 + wm + mt * 16 + g8;
            OT* crow0 = C + (size_t)m * HH;
            OT* crow1 = crow0 + 8 * HH;
#pragma unroll
            for (int nt = 0; nt < 4; nt++) {
                const int n = col0 + wn + nt * 8 + 2 * t4;
                const float b0 = bias[n], b1 = bias[n + 1];
                float v0 = acc[mt][nt][0] + b0;
                float v1 = acc[mt][nt][1] + b1;
                float v2 = acc[mt][nt][2] + b0;
                float v3 = acc[mt][nt][3] + b1;
                if (GELU) {
                    v0 = gelu_exact(v0); v1 = gelu_exact(v1);
                    v2 = gelu_exact(v2); v3 = gelu_exact(v3);
                }
                if (sizeof(OT) == 2) {
                    *(__half2*)(crow0 + n) = __floats2half2_rn(v0, v1);
                    *(__half2*)(crow1 + n) = __floats2half2_rn(v2, v3);
                } else {
                    *(float2*)((float*)crow0 + n) = make_float2(v0, v1);
                    *(float2*)((float*)crow1 + n) = make_float2(v2, v3);
                }
            }
        }
    }
}

// conv GEMMs: tiles 0..511 = approx, 512..1023 = detail
__global__ __launch_bounds__(256, 2)
void conv_gemm(const __grid_constant__ CUtensorMap tmAca,
               const __grid_constant__ CUtensorMap tmAcd,
               const __grid_constant__ CUtensorMap tmBa,
               const __grid_constant__ CUtensorMap tmBd,
               const float* __restrict__ bias_a, const float* __restrict__ bias_d) {
    extern __shared__ __align__(1024) char smem[];
    persistent_gemm<true, true, __half>(&tmAca, &tmAcd, &tmBa, &tmBd,
                                        bias_a, bias_d, g_pa, g_pd, 1024, 48, smem);
}

__global__ __launch_bounds__(256, 2)
void out_gemm(const __grid_constant__ CUtensorMap tmA,
              const __grid_constant__ CUtensorMap tmB,
              const float* __restrict__ b_out, float* __restrict__ out) {
    extern __shared__ __align__(1024) char smem[];
    persistent_gemm<false, false, float>(&tmA, &tmA, &tmB, &tmB,
                                         b_out, b_out, out, out, 1024, 16, smem);
}

// ---------------------------------------------------------------------------
typedef CUresult (*PFN_encode)(
    CUtensorMap*, CUtensorMapDataType, cuuint32_t, void*,
    const cuuint64_t*, const cuuint64_t*, const cuuint32_t*, const cuuint32_t*,
    CUtensorMapInterleave, CUtensorMapSwizzle, CUtensorMapL2promotion,
    CUtensorMapFloatOOBfill);

static void enc2d(PFN_encode enc, CUtensorMap* tm, void* base,
                  unsigned long long inner, unsigned long long rows) {
    cuuint64_t dims[2] = {inner, rows};
    cuuint64_t strides[1] = {inner * 2};
    cuuint32_t box[2] = {64, 128};
    cuuint32_t es[2] = {1, 1};
    enc(tm, CU_TENSOR_MAP_DATA_TYPE_UINT16, 2, base, dims, strides, box, es,
        CU_TENSOR_MAP_INTERLEAVE_NONE, CU_TENSOR_MAP_SWIZZLE_128B,
        CU_TENSOR_MAP_L2_PROMOTION_L2_128B, CU_TENSOR_MAP_FLOAT_OOB_FILL_NONE);
}

extern "C" void kernel_launch(void* const* d_in, const int* in_sizes, int n_in,
                              void* d_out, int out_size) {
    const float* x        = (const float*)d_in[0];
    const float* w_approx = (const float*)d_in[1];
    const float* b_approx = (const float*)d_in[2];
    const float* w_detail = (const float*)d_in[3];
    const float* b_detail = (const float*)d_in[4];
    const float* w_out    = (const float*)d_in[5];
    const float* b_out    = (const float*)d_in[6];
    float* out = (float*)d_out;

    cudaFuncSetAttribute(conv_gemm, cudaFuncAttributeMaxDynamicSharedMemorySize, SMEM_BYTES);
    cudaFuncSetAttribute(out_gemm, cudaFuncAttributeMaxDynamicSharedMemorySize, SMEM_BYTES);

    int smCount = 148;
    cudaDeviceGetAttribute(&smCount, cudaDevAttrMultiProcessorCount, 0);
    const int nPersist = smCount * 2;

    void *p_ca, *p_cd, *p_rec, *p_wc, *p_wo;
    cudaGetSymbolAddress(&p_ca, g_ca);
    cudaGetSymbolAddress(&p_cd, g_cd);
    cudaGetSymbolAddress(&p_rec, g_rec);
    cudaGetSymbolAddress(&p_wc, g_wc);
    cudaGetSymbolAddress(&p_wo, g_wo);

    void* fn = nullptr;
    cudaDriverEntryPointQueryResult qr;
    cudaGetDriverEntryPoint("cuTensorMapEncodeTiled", &fn, cudaEnableDefault, &qr);
    PFN_encode enc = (PFN_encode)fn;

    CUtensorMap tmAca, tmAcd, tmBa, tmBd, tmArec, tmBo;
    enc2d(enc, &tmAca, p_ca, 1024, (unsigned long long)NB * MP);
    enc2d(enc, &tmAcd, p_cd, 1024, (unsigned long long)NB * MP);
    enc2d(enc, &tmBa, p_wc, 3072, 1024);
    enc2d(enc, &tmBd, (char*)p_wc + (size_t)HH * 3072 * 2, 3072, 1024);
    enc2d(enc, &tmArec, p_rec, 1024, (unsigned long long)NB * SS);
    enc2d(enc, &tmBo, p_wo, 1024, 1024);

    // fused weight prep: 8192 blocks conv + 4096 blocks out
    prep_weights<<<12288, 256>>>(w_approx, w_detail, w_out);
    // fused DWT + zero-pad
    dwt_kernel<<<NB * MM + 16, 256>>>(x);

    // conv GEMMs: persistent, 1024 tiles (approx + detail), K=3072
    conv_gemm<<<nPersist, 256, SMEM_BYTES>>>(tmAca, tmAcd, tmBa, tmBd,
                                             b_approx, b_detail);

    // paired iDWT, wide: one block per (b, t), 128 threads x 8 halves
    idwt_kernel<<<NB * MM, 128>>>();

    // out GEMM: persistent, 1024 tiles, K=1024
    out_gemm<<<nPersist, 256, SMEM_BYTES>>>(tmArec, tmBo, b_out, out);
}

// round 15
// speedup vs baseline: 1.1240x; 1.0115x over previous
#include <cuda_runtime.h>
#include <cuda.h>
#include <cuda_fp16.h>
#include <math.h>
#include <stdint.h>

#define NB 8
#define SS 2048
#define HH 1024
#define MM 1024
#define MP 1026   // padded rows per batch (zero row below m=0 and above m=1023)

#define C_H0 0.48296291314469025f
#define C_H1 0.83651630373780790f
#define C_H2 0.22414386804185735f
#define C_H3 (-0.12940952255092145f)

// GEMM tiling: CTA 128x128, BK=64, 3-stage TMA pipeline, SW128
// 8 warps (256 threads), warp tile 64x32 (2x4 warp grid), persistent CTAs
#define BK 64
#define TILEB 16384           // 128 rows x 128B per operand tile
#define STAGEB (2 * TILEB)    // A + B
#define SMEM_BYTES (3 * STAGEB + 64)

// prologue kernel block split
#define PREP_BLOCKS 12288     // weight conversion
#define DWT_BLOCKS  4096      // 8 batches x 512 m-pairs
#define PAD_BLOCKS  16

// ---------------- device scratch ----------------
__device__ __align__(16) __half g_ca[NB * MP * HH];
__device__ __align__(16) __half g_cd[NB * MP * HH];
__device__ __align__(16) __half g_pa[NB * MM * HH];
__device__ __align__(16) __half g_pd[NB * MM * HH];
__device__ __align__(16) __half g_rec[NB * SS * HH];
__device__ __align__(16) __half g_wc[2 * HH * 3072];  // [which][o][delta*1024+h]
__device__ __align__(16) __half g_wo[HH * HH];        // [o][h]

// ---------------- helpers ----------------
__device__ __forceinline__ uint32_t smem_u32(const void* p) {
    uint32_t a;
    asm("{ .reg .u64 t; cvta.to.shared.u64 t, %1; cvt.u32.u64 %0, t; }" : "=r"(a) : "l"(p));
    return a;
}

__device__ __forceinline__ uint32_t sw128(uint32_t o) {  // SW128: bits[6:4] ^= bits[9:7]
    return o ^ ((o >> 3) & 0x70);
}

__device__ __forceinline__ void ldm_x4(uint32_t& r0, uint32_t& r1, uint32_t& r2, uint32_t& r3,
                                       uint32_t addr) {
    asm volatile("ldmatrix.sync.aligned.m8n8.x4.shared.b16 {%0,%1,%2,%3}, [%4];"
                 : "=r"(r0), "=r"(r1), "=r"(r2), "=r"(r3) : "r"(addr));
}

__device__ __forceinline__ void mma16816(float* d, const uint32_t* a, const uint32_t* b) {
    asm volatile(
        "mma.sync.aligned.m16n8k16.row.col.f32.f16.f16.f32 "
        "{%0,%1,%2,%3}, {%4,%5,%6,%7}, {%8,%9}, {%0,%1,%2,%3};"
        : "+f"(d[0]), "+f"(d[1]), "+f"(d[2]), "+f"(d[3])
        : "r"(a[0]), "r"(a[1]), "r"(a[2]), "r"(a[3]), "r"(b[0]), "r"(b[1]));
}

__device__ __forceinline__ void tma2d(uint32_t dst, const CUtensorMap* tm, int x, int y,
                                      uint32_t mb) {
    asm volatile(
        "cp.async.bulk.tensor.2d.shared::cta.global.tile.mbarrier::complete_tx::bytes "
        "[%0], [%1, {%2, %3}], [%4];"
        :: "r"(dst), "l"(tm), "r"(x), "r"(y), "r"(mb) : "memory");
}

__device__ __forceinline__ void mbar_init(uint32_t mb, uint32_t cnt) {
    asm volatile("mbarrier.init.shared.b64 [%0], %1;" :: "r"(mb), "r"(cnt) : "memory");
}

__device__ __forceinline__ void mbar_expect(uint32_t mb, uint32_t bytes) {
    asm volatile("mbarrier.arrive.expect_tx.shared.b64 _, [%0], %1;"
                 :: "r"(mb), "r"(bytes) : "memory");
}

__device__ __forceinline__ void mbar_wait(uint32_t mb, uint32_t parity) {
    asm volatile(
        "{\n\t.reg .pred P;\n\t"
        "LAB_%=:\n\t"
        "mbarrier.try_wait.parity.acquire.cta.shared::cta.b64 P, [%0], %1, 0x989680;\n\t"
        "@!P bra LAB_%=;\n\t"
        "}" :: "r"(mb), "r"(parity) : "memory");
}

__device__ __forceinline__ float gelu_exact(float v) {
    return 0.5f * v * (1.0f + erff(v * 0.70710678118654752f));
}

// ---------------------------------------------------------------------------
// Fused prologue: weight prep (blocks 0..12287), paired DWT (next 4096),
// boundary zero rows (last 16). All independent; one launch.
// ---------------------------------------------------------------------------
__global__ void prologue_kernel(const float* __restrict__ x,
                                const float* __restrict__ wA,
                                const float* __restrict__ wD,
                                const float* __restrict__ wO) {
    const int blk = blockIdx.x;
    const int tid = threadIdx.x;

    if (blk < PREP_BLOCKS) {
        int idx = blk * 256 + tid;
        if (idx < (2 << 20)) {               // conv weights: 2 * 1M entries (o,h)
            int which = idx >> 20;
            int oh = idx & ((1 << 20) - 1);
            int o = oh >> 10, h = oh & 1023;
            const float* w = which ? wD : wA;
            __half* W = g_wc + (size_t)which * HH * 3072;
            const float* p = w + ((size_t)o * HH + h) * 3;
#pragma unroll
            for (int d = 0; d < 3; d++)
                W[(size_t)o * 3072 + d * 1024 + h] = __float2half_rn(p[d]);
        } else {                             // out weights: 1M entries
            int j = idx - (2 << 20);
            g_wo[j] = __float2half_rn(wO[j]);
        }
        return;
    }

    if (blk < PREP_BLOCKS + DWT_BLOCKS) {
        // paired DWT: block computes m0=2j and m1=2j+1 sharing rows 4j,4j+1.
        // ca[m] = h0 x[2m-2] + h1 x[2m-1] + h2 x[2m] + h3 x[2m+1]
        // cd[m] = h3 x[2m-2] - h2 x[2m-1] + h1 x[2m] - h0 x[2m+1]
        const int bj = blk - PREP_BLOCKS;
        const int b = bj >> 9, j = bj & 511;
        const int h = tid << 2;
        int r0 = 4 * j - 2, r1 = 4 * j - 1;
        if (r0 < 0) r0 = -r0 - 1;            // symmetric reflection (j==0 only)
        if (r1 < 0) r1 = -r1 - 1;
        const float* xb = x + (size_t)b * SS * HH + h;
        float4 v0 = *(const float4*)(xb + (size_t)r0 * HH);
        float4 v1 = *(const float4*)(xb + (size_t)r1 * HH);
        float4 v2 = *(const float4*)(xb + (size_t)(4 * j) * HH);
        float4 v3 = *(const float4*)(xb + (size_t)(4 * j + 1) * HH);
        float4 v4 = *(const float4*)(xb + (size_t)(4 * j + 2) * HH);
        float4 v5 = *(const float4*)(xb + (size_t)(4 * j + 3) * HH);

        __half ca0[4], cd0[4], ca1[4], cd1[4];
        const float* p0 = (const float*)&v0;
        const float* p1 = (const float*)&v1;
        const float* p2 = (const float*)&v2;
        const float* p3 = (const float*)&v3;
        const float* p4 = (const float*)&v4;
        const float* p5 = (const float*)&v5;
#pragma unroll
        for (int e = 0; e < 4; e++) {
            ca0[e] = __float2half_rn(C_H0 * p0[e] + C_H1 * p1[e] + C_H2 * p2[e] + C_H3 * p3[e]);
            cd0[e] = __float2half_rn(C_H3 * p0[e] - C_H2 * p1[e] + C_H1 * p2[e] - C_H0 * p3[e]);
            ca1[e] = __float2half_rn(C_H0 * p2[e] + C_H1 * p3[e] + C_H2 * p4[e] + C_H3 * p5[e]);
            cd1[e] = __float2half_rn(C_H3 * p2[e] - C_H2 * p3[e] + C_H1 * p4[e] - C_H0 * p5[e]);
        }
        size_t off0 = ((size_t)b * MP + 2 * j + 1) * HH + h;   // padded row m0+1
        *(uint2*)(g_ca + off0) = *(const uint2*)ca0;
        *(uint2*)(g_cd + off0) = *(const uint2*)cd0;
        *(uint2*)(g_ca + off0 + HH) = *(const uint2*)ca1;
        *(uint2*)(g_cd + off0 + HH) = *(const uint2*)cd1;
        return;
    }

    // boundary zero rows
    const int j = blk - PREP_BLOCKS - DWT_BLOCKS;
    const int b = j >> 1;
    const int top = j & 1;
    size_t off = ((size_t)b * MP + (top ? 1025 : 0)) * HH + tid * 4;
    uint2 z = make_uint2(0u, 0u);
    *(uint2*)(g_ca + off) = z;
    *(uint2*)(g_cd + off) = z;
}

// ---------------- paired iDWT, wide: 128 threads x 8 halves (uint4) ----------
// even (n=2t):   H2*pa[t] + H0*pa[t+1] + H1*pd[t] + H3*pd[t+1]
// odd  (n=2t+1): H3*pa[t] + H1*pa[t+1] - H0*pd[t] - H2*pd[t+1]
__global__ void idwt_kernel() {
    int bt = blockIdx.x;
    int b = bt >> 10, t = bt & 1023;
    int h = threadIdx.x << 3;
    size_t outoff = ((size_t)b * SS + 2 * t) * HH + h;
    if (t == 1023) {   // rows 2046, 2047 are zero
        uint4 z = make_uint4(0u, 0u, 0u, 0u);
        *(uint4*)(g_rec + outoff) = z;
        *(uint4*)(g_rec + outoff + HH) = z;
        return;
    }
    size_t base = (size_t)b * MM * HH + h + (size_t)t * HH;
    uint4 ua0 = *(const uint4*)(g_pa + base);
    uint4 ua1 = *(const uint4*)(g_pa + base + HH);
    uint4 ud0 = *(const uint4*)(g_pd + base);
    uint4 ud1 = *(const uint4*)(g_pd + base + HH);
    const __half2* a0 = (const __half2*)&ua0;
    const __half2* a1 = (const __half2*)&ua1;
    const __half2* d0 = (const __half2*)&ud0;
    const __half2* d1 = (const __half2*)&ud1;
    uint4 evo, odo;
    __half2* ev = (__half2*)&evo;
    __half2* od = (__half2*)&odo;
#pragma unroll
    for (int q = 0; q < 4; q++) {
        float2 fa0 = __half22float2(a0[q]);
        float2 fa1 = __half22float2(a1[q]);
        float2 fd0 = __half22float2(d0[q]);
        float2 fd1 = __half22float2(d1[q]);
        ev[q] = __floats2half2_rn(
            C_H2 * fa0.x + C_H0 * fa1.x + C_H1 * fd0.x + C_H3 * fd1.x,
            C_H2 * fa0.y + C_H0 * fa1.y + C_H1 * fd0.y + C_H3 * fd1.y);
        od[q] = __floats2half2_rn(
            C_H3 * fa0.x + C_H1 * fa1.x - C_H0 * fd0.x - C_H2 * fd1.x,
            C_H3 * fa0.y + C_H1 * fa1.y - C_H0 * fd0.y - C_H2 * fd1.y);
    }
    *(uint4*)(g_rec + outoff) = evo;
    *(uint4*)(g_rec + outoff + HH) = odo;
}

// ---------------------------------------------------------------------------
// Persistent fp16 GEMM, TMA-fed, continuous 3-stage pipeline (R12/R14):
// a CTA processes tiles blockIdx.x, +gridDim.x, ... with a CONTINUOUS global
// chunk counter g (stage=g%3, parity=(g/3)&1). Producer issues chunk g+2,
// which near tile boundaries belongs to the NEXT tile, so its loads overlap
// this tile's epilogue.
// ---------------------------------------------------------------------------
template <bool CONV, bool GELU, typename OT>
__device__ __forceinline__ void persistent_gemm(
    const CUtensorMap* tmA0, const CUtensorMap* tmA1,
    const CUtensorMap* tmB0, const CUtensorMap* tmB1,
    const float* __restrict__ bias0, const float* __restrict__ bias1,
    OT* __restrict__ C0, OT* __restrict__ C1,
    int nTiles, int kChunks, char* smem) {

    const uint32_t sbase = smem_u32(smem);
    const uint32_t mbars = sbase + 3 * STAGEB;

    const int tid = threadIdx.x;
    const int lane = tid & 31;
    const int wid = tid >> 5;

    const int nMine = (nTiles - (int)blockIdx.x + (int)gridDim.x - 1) / (int)gridDim.x;
    if (nMine <= 0) return;
    const int totalC = nMine * kChunks;

    if (tid == 0) {
        mbar_init(mbars + 0, 1);
        mbar_init(mbars + 8, 1);
        mbar_init(mbars + 16, 1);
    }
    __syncthreads();

    // issue chunk with global (per-CTA) index gg
    auto issue = [&](int gg) {
        const int tL = gg / kChunks;
        const int c2 = gg - tL * kChunks;
        const int tile2 = (int)blockIdx.x + tL * (int)gridDim.x;
        const int which2 = CONV ? (tile2 >> 9) : 0;
        const int row02 = CONV ? (((tile2 >> 3) & 63) << 7) : ((tile2 >> 3) << 7);
        const int col02 = (tile2 & 7) << 7;
        const int k0 = c2 * BK;
        int ax, ay;
        if (CONV) {
            ax = k0 & 1023;
            ay = (row02 >> 10) * MP + (row02 & 1023) + (k0 >> 10);
        } else {
            ax = k0;
            ay = row02;
        }
        const int s2 = gg % 3;
        const uint32_t mb = mbars + s2 * 8;
        mbar_expect(mb, 2 * TILEB);
        tma2d(sbase + s2 * STAGEB, which2 ? tmA1 : tmA0, ax, ay, mb);
        tma2d(sbase + s2 * STAGEB + TILEB, which2 ? tmB1 : tmB0, k0, col02, mb);
    };

    if (tid == 0) {
        issue(0);
        if (totalC > 1) issue(1);
    }

    // warp grid 2x4, warp tile 64x32
    const int wm = (wid >> 2) * 64;
    const int wn = (wid & 3) * 32;
    const uint32_t aBase = (uint32_t)((wm + (lane & 15)) * 128 + ((lane >> 4) << 4));
    const uint32_t bBase = (uint32_t)((wn + (lane & 7) + ((lane >> 4) << 3)) * 128 +
                                      (((lane >> 3) & 1) << 4));
    const int g8 = lane >> 2, t4 = lane & 3;

    int g = 0;
    for (int myT = 0; myT < nMine; myT++) {
        const int tile = (int)blockIdx.x + myT * (int)gridDim.x;
        const int which = CONV ? (tile >> 9) : 0;
        const int row0 = CONV ? (((tile >> 3) & 63) << 7) : ((tile >> 3) << 7);
        const int col0 = (tile & 7) << 7;
        const float* bias = which ? bias1 : bias0;
        OT* C = which ? C1 : C0;

        float acc[4][4][4];
#pragma unroll
        for (int i = 0; i < 4; i++)
#pragma unroll
            for (int j = 0; j < 4; j++)
#pragma unroll
                for (int e = 0; e < 4; e++) acc[i][j][e] = 0.0f;

        for (int c = 0; c < kChunks; c++, g++) {
            __syncthreads();   // everyone done with stage (g+2)%3's previous use
            if (tid == 0 && g + 2 < totalC) issue(g + 2);

            const int s = g % 3;
            mbar_wait(mbars + s * 8, (uint32_t)((g / 3) & 1));

            const uint32_t stA = sbase + s * STAGEB;
            const uint32_t stB = stA + TILEB;
#pragma unroll
            for (int kk = 0; kk < 4; kk++) {
                uint32_t af[4][4];
#pragma unroll
                for (int mt = 0; mt < 4; mt++) {
                    const uint32_t lo = aBase + mt * (16 * 128) + kk * 32;
                    ldm_x4(af[mt][0], af[mt][1], af[mt][2], af[mt][3], stA + sw128(lo));
                }
                uint32_t bf[4][2];
#pragma unroll
                for (int nt2 = 0; nt2 < 2; nt2++) {
                    const uint32_t lo = bBase + nt2 * (16 * 128) + kk * 32;
                    ldm_x4(bf[2 * nt2][0], bf[2 * nt2][1], bf[2 * nt2 + 1][0],
                           bf[2 * nt2 + 1][1], stB + sw128(lo));
                }
#pragma unroll
                for (int mt = 0; mt < 4; mt++)
#pragma unroll
                    for (int nt = 0; nt < 4; nt++)
                        mma16816(acc[mt][nt], af[mt], bf[nt]);
            }
        }

        // ---- epilogue (overlaps with TMA of next tile's first chunks)
#pragma unroll
        for (int mt = 0; mt < 4; mt++) {
            const int m = row0 + wm + mt * 16 + g8;
            OT* crow0 = C + (size_t)m * HH;
            OT* crow1 = crow0 + 8 * HH;
#pragma unroll
            for (int nt = 0; nt < 4; nt++) {
                const int n = col0 + wn + nt * 8 + 2 * t4;
                const float b0 = bias[n], b1 = bias[n + 1];
                float v0 = acc[mt][nt][0] + b0;
                float v1 = acc[mt][nt][1] + b1;
                float v2 = acc[mt][nt][2] + b0;
                float v3 = acc[mt][nt][3] + b1;
                if (GELU) {
                    v0 = gelu_exact(v0); v1 = gelu_exact(v1);
                    v2 = gelu_exact(v2); v3 = gelu_exact(v3);
                }
                if (sizeof(OT) == 2) {
                    *(__half2*)(crow0 + n) = __floats2half2_rn(v0, v1);
                    *(__half2*)(crow1 + n) = __floats2half2_rn(v2, v3);
                } else {
                    *(float2*)((float*)crow0 + n) = make_float2(v0, v1);
                    *(float2*)((float*)crow1 + n) = make_float2(v2, v3);
                }
            }
        }
    }
}

// conv GEMMs: tiles 0..511 = approx, 512..1023 = detail
__global__ __launch_bounds__(256, 2)
void conv_gemm(const __grid_constant__ CUtensorMap tmAca,
               const __grid_constant__ CUtensorMap tmAcd,
               const __grid_constant__ CUtensorMap tmBa,
               const __grid_constant__ CUtensorMap tmBd,
               const float* __restrict__ bias_a, const float* __restrict__ bias_d) {
    extern __shared__ __align__(1024) char smem[];
    persistent_gemm<true, true, __half>(&tmAca, &tmAcd, &tmBa, &tmBd,
                                        bias_a, bias_d, g_pa, g_pd, 1024, 48, smem);
}

__global__ __launch_bounds__(256, 2)
void out_gemm(const __grid_constant__ CUtensorMap tmA,
              const __grid_constant__ CUtensorMap tmB,
              const float* __restrict__ b_out, float* __restrict__ out) {
    extern __shared__ __align__(1024) char smem[];
    persistent_gemm<false, false, float>(&tmA, &tmA, &tmB, &tmB,
                                         b_out, b_out, out, out, 1024, 16, smem);
}

// ---------------------------------------------------------------------------
typedef CUresult (*PFN_encode)(
    CUtensorMap*, CUtensorMapDataType, cuuint32_t, void*,
    const cuuint64_t*, const cuuint64_t*, const cuuint32_t*, const cuuint32_t*,
    CUtensorMapInterleave, CUtensorMapSwizzle, CUtensorMapL2promotion,
    CUtensorMapFloatOOBfill);

static void enc2d(PFN_encode enc, CUtensorMap* tm, void* base,
                  unsigned long long inner, unsigned long long rows) {
    cuuint64_t dims[2] = {inner, rows};
    cuuint64_t strides[1] = {inner * 2};
    cuuint32_t box[2] = {64, 128};
    cuuint32_t es[2] = {1, 1};
    enc(tm, CU_TENSOR_MAP_DATA_TYPE_UINT16, 2, base, dims, strides, box, es,
        CU_TENSOR_MAP_INTERLEAVE_NONE, CU_TENSOR_MAP_SWIZZLE_128B,
        CU_TENSOR_MAP_L2_PROMOTION_L2_128B, CU_TENSOR_MAP_FLOAT_OOB_FILL_NONE);
}

extern "C" void kernel_launch(void* const* d_in, const int* in_sizes, int n_in,
                              void* d_out, int out_size) {
    const float* x        = (const float*)d_in[0];
    const float* w_approx = (const float*)d_in[1];
    const float* b_approx = (const float*)d_in[2];
    const float* w_detail = (const float*)d_in[3];
    const float* b_detail = (const float*)d_in[4];
    const float* w_out    = (const float*)d_in[5];
    const float* b_out    = (const float*)d_in[6];
    float* out = (float*)d_out;

    cudaFuncSetAttribute(conv_gemm, cudaFuncAttributeMaxDynamicSharedMemorySize, SMEM_BYTES);
    cudaFuncSetAttribute(out_gemm, cudaFuncAttributeMaxDynamicSharedMemorySize, SMEM_BYTES);

    int smCount = 148;
    cudaDeviceGetAttribute(&smCount, cudaDevAttrMultiProcessorCount, 0);
    const int nPersist = smCount * 2;

    void *p_ca, *p_cd, *p_rec, *p_wc, *p_wo;
    cudaGetSymbolAddress(&p_ca, g_ca);
    cudaGetSymbolAddress(&p_cd, g_cd);
    cudaGetSymbolAddress(&p_rec, g_rec);
    cudaGetSymbolAddress(&p_wc, g_wc);
    cudaGetSymbolAddress(&p_wo, g_wo);

    void* fn = nullptr;
    cudaDriverEntryPointQueryResult qr;
    cudaGetDriverEntryPoint("cuTensorMapEncodeTiled", &fn, cudaEnableDefault, &qr);
    PFN_encode enc = (PFN_encode)fn;

    CUtensorMap tmAca, tmAcd, tmBa, tmBd, tmArec, tmBo;
    enc2d(enc, &tmAca, p_ca, 1024, (unsigned long long)NB * MP);
    enc2d(enc, &tmAcd, p_cd, 1024, (unsigned long long)NB * MP);
    enc2d(enc, &tmBa, p_wc, 3072, 1024);
    enc2d(enc, &tmBd, (char*)p_wc + (size_t)HH * 3072 * 2, 3072, 1024);
    enc2d(enc, &tmArec, p_rec, 1024, (unsigned long long)NB * SS);
    enc2d(enc, &tmBo, p_wo, 1024, 1024);

    // fused prologue: weight prep + paired DWT + zero-pad, one launch
    prologue_kernel<<<PREP_BLOCKS + DWT_BLOCKS + PAD_BLOCKS, 256>>>(
        x, w_approx, w_detail, w_out);

    // conv GEMMs: persistent, 1024 tiles (approx + detail), K=3072
    conv_gemm<<<nPersist, 256, SMEM_BYTES>>>(tmAca, tmAcd, tmBa, tmBd,
                                             b_approx, b_detail);

    // paired iDWT, wide: one block per (b, t), 128 threads x 8 halves
    idwt_kernel<<<NB * MM, 128>>>();

    // out GEMM: persistent, 1024 tiles, K=1024
    out_gemm<<<nPersist, 256, SMEM_BYTES>>>(tmArec, tmBo, b_out, out);
}